// round 8
// baseline (speedup 1.0000x reference)
#include <cuda_runtime.h>
#include <cuda_bf16.h>
#include <cub/cub.cuh>
#include <math.h>

#define HFE 100
#define WFE 152
#define HW  15200
#define CMID 512
#define KTOT 4608           // 9 taps * 512 channels
#define PADH 102
#define PADW 154
#define PADHW (PADH*PADW)   // 15708
#define NBOX 136800
#define NPRE 6000
#define NPOST 300
#define OUT_LOC 0
#define OUT_SC  547200
#define OUT_ROI 820800
#define IMG_H 1600.0f
#define IMG_W 2432.0f
#define NEG_INF (__int_as_float(0xff800000))

// conv tiling
#define TM 128
#define TN 128
#define ROWB 80              // padded row bytes (32 bf16 = 64B data + 16B pad)
#define TILEB (128*ROWB)     // 10240 per tile
#define NTILE 6              // Ah Am Al Bh Bm Bl
#define STAGEB (NTILE*TILEB) // 61440
#define NSTAGE 144           // 9 taps * 16 channel-chunks (32ch each)
#define SMEM_CONV (2*STAGEB) // 122880

// ---------------- device scratch ----------------
__device__ __align__(256) __nv_bfloat16 g_wh[CMID * KTOT];   // [m][k], k=t*512+c
__device__ __align__(256) __nv_bfloat16 g_wm[CMID * KTOT];
__device__ __align__(256) __nv_bfloat16 g_wl[CMID * KTOT];
__device__ __align__(256) __nv_bfloat16 g_xh[PADHW * 512];   // [padrow][c]
__device__ __align__(256) __nv_bfloat16 g_xm[PADHW * 512];
__device__ __align__(256) __nv_bfloat16 g_xl[PADHW * 512];
__device__ __align__(16)  float g_h[(size_t)CMID * HW];      // conv1 out [m][p]
__device__ float g_roi[NBOX * 4];
__device__ float g_sc[NBOX];
__device__ unsigned g_idx[NBOX];
__device__ float g_sc_s[NBOX];
__device__ unsigned g_idx_s[NBOX];
__device__ unsigned char g_tmp[32 << 20];

__constant__ int c_dy[9] = {-1,-1,-1, 0,0,0, 1,1,1};
__constant__ int c_dx[9] = {-1, 0, 1,-1,0,1,-1,0,1};

// ---------------- PTX helpers (compute_103-safe: sm_80 base features only) ----
__device__ __forceinline__ uint32_t smem_u32(const void* p) {
    uint32_t a;
    asm("{ .reg .u64 t; cvta.to.shared.u64 t, %1; cvt.u32.u64 %0, t; }" : "=r"(a) : "l"(p));
    return a;
}
__device__ __forceinline__ void cp16(uint32_t dst, const void* src) {
    asm volatile("cp.async.cg.shared.global [%0], [%1], 16;" :: "r"(dst), "l"(src));
}
__device__ __forceinline__ void cp_commit() {
    asm volatile("cp.async.commit_group;" ::: "memory");
}
__device__ __forceinline__ void cp_wait1() {
    asm volatile("cp.async.wait_group 1;" ::: "memory");
}
__device__ __forceinline__ void cp_wait0() {
    asm volatile("cp.async.wait_group 0;" ::: "memory");
}
__device__ __forceinline__ void ldm_x4(uint32_t& r0, uint32_t& r1, uint32_t& r2, uint32_t& r3,
                                       uint32_t a) {
    asm volatile("ldmatrix.sync.aligned.m8n8.x4.shared.b16 {%0,%1,%2,%3}, [%4];"
                 : "=r"(r0), "=r"(r1), "=r"(r2), "=r"(r3) : "r"(a));
}
__device__ __forceinline__ void mma16816(float* c, const uint32_t* a, const uint32_t* b) {
    asm volatile(
        "mma.sync.aligned.m16n8k16.row.col.f32.bf16.bf16.f32 "
        "{%0,%1,%2,%3}, {%4,%5,%6,%7}, {%8,%9}, {%0,%1,%2,%3};"
        : "+f"(c[0]), "+f"(c[1]), "+f"(c[2]), "+f"(c[3])
        : "r"(a[0]), "r"(a[1]), "r"(a[2]), "r"(a[3]), "r"(b[0]), "r"(b[1]));
}

// ---------------- prep: zero padded x arrays ----------------
__global__ void k_fill()
{
    int i = blockIdx.x * 256 + threadIdx.x;
    uint4 z = make_uint4(0, 0, 0, 0);
    int n4 = PADHW * 512 / 8;
    if (i < n4) {
        reinterpret_cast<uint4*>(g_xh)[i] = z;
        reinterpret_cast<uint4*>(g_xm)[i] = z;
        reinterpret_cast<uint4*>(g_xl)[i] = z;
    }
}

// ---------------- prep: x 3-term split + transpose + pad ----------------
__global__ void k_xsplit(const float* __restrict__ x)
{
    __shared__ float tile[32][33];
    int p0 = blockIdx.x * 32;
    int c0 = blockIdx.y * 32;
    int tx = threadIdx.x, ty = threadIdx.y;
    tile[ty][tx] = x[(c0 + ty) * HW + p0 + tx];
    __syncthreads();
    int p = p0 + ty;
    int py = p / WFE, px = p - py * WFE;
    int row = (py + 1) * PADW + px + 1;
    float v = tile[tx][ty];
    __nv_bfloat16 hi = __float2bfloat16_rn(v);
    float r1 = v - __bfloat162float(hi);
    __nv_bfloat16 md = __float2bfloat16_rn(r1);
    __nv_bfloat16 lo = __float2bfloat16_rn(r1 - __bfloat162float(md));
    g_xh[row * 512 + c0 + tx] = hi;
    g_xm[row * 512 + c0 + tx] = md;
    g_xl[row * 512 + c0 + tx] = lo;
}

// ---------------- prep: weight 3-term split + reorder ----------------
__global__ void k_wsplit(const float* __restrict__ w1)
{
    __shared__ float wrow[KTOT];
    int m = blockIdx.x;
    for (int i = threadIdx.x; i < KTOT; i += 256)
        wrow[i] = w1[m * KTOT + i];           // [c][t] order
    __syncthreads();
    for (int j = threadIdx.x; j < KTOT; j += 256) {
        int t = j >> 9, c = j & 511;
        float v = wrow[c * 9 + t];
        __nv_bfloat16 hi = __float2bfloat16_rn(v);
        float r1 = v - __bfloat162float(hi);
        __nv_bfloat16 md = __float2bfloat16_rn(r1);
        __nv_bfloat16 lo = __float2bfloat16_rn(r1 - __bfloat162float(md));
        g_wh[m * KTOT + j] = hi;
        g_wm[m * KTOT + j] = md;
        g_wl[m * KTOT + j] = lo;
    }
}

// ---------------- conv 3x3 via mma.sync bf16 (exact 3-term split, 6 products) --
// kept products: hh | hm mh hl lh mm; hh -> accH (clean fp32 chain),
// small terms -> accL (their rounding noise is 2^-9 down); sum at epilogue.
__global__ __launch_bounds__(256, 1) void k_convmma(const float* __restrict__ bias)
{
    extern __shared__ char smc[];
    const uint32_t smb = smem_u32(smc);
    const int tid = threadIdx.x;
    const int n0 = blockIdx.x * TN;
    const int m0 = blockIdx.y * TM;

    // ---- loader geometry: 3 row-tasks per thread (6 tiles x 128 rows / 256) ----
    int task_tile[3];
    const __nv_bfloat16* task_base[3];
    uint32_t task_dst[3];
#pragma unroll
    for (int j = 0; j < 3; j++) {
        int r = j * 256 + tid;
        int tile = r >> 7;
        int row = r & 127;
        task_tile[j] = tile;
        task_dst[j] = smb + tile * TILEB + row * ROWB;
        if (tile < 3) {
            const __nv_bfloat16* gw = (tile == 0) ? g_wh : (tile == 1) ? g_wm : g_wl;
            task_base[j] = gw + (size_t)(m0 + row) * KTOT;
        } else {
            const __nv_bfloat16* gx = (tile == 3) ? g_xh : (tile == 4) ? g_xm : g_xl;
            int p = min(n0 + row, HW - 1);
            int py = p / WFE, px = p - py * WFE;
            task_base[j] = gx + (size_t)((py + 1) * PADW + px + 1) * 512;
        }
    }

    auto issue_loads = [&](int s, int buf) {
        const int t = s >> 4;
        const int c0 = (s & 15) << 5;
        const int woff = t * 512 + c0;
        const int xoff = (c_dy[t] * PADW + c_dx[t]) * 512 + c0;
        const uint32_t boff = buf * STAGEB;
#pragma unroll
        for (int j = 0; j < 3; j++) {
            const __nv_bfloat16* p = task_base[j] + (task_tile[j] < 3 ? woff : xoff);
            uint32_t d = task_dst[j] + boff;
#pragma unroll
            for (int q = 0; q < 4; q++) cp16(d + q * 16, p + q * 8);
        }
        cp_commit();
    };

    // ---- compute geometry ----
    const int w = tid >> 5;
    const int l = tid & 31;
    const int m_w = (w >> 2) * 64;    // 0 or 64
    const int n_w = (w & 3) * 32;     // 0,32,64,96
    const uint32_t apos = ((l & 7) + ((l >> 3) & 1) * 8) * ROWB + (l >> 4) * 16;
    const uint32_t bpos = ((l & 7) + (l >> 4) * 8) * ROWB + ((l >> 3) & 1) * 16;

    float accH[4][4][4];
    float accL[4][4][4];
#pragma unroll
    for (int mi = 0; mi < 4; mi++)
#pragma unroll
        for (int ni = 0; ni < 4; ni++)
#pragma unroll
            for (int q = 0; q < 4; q++) { accH[mi][ni][q] = 0.f; accL[mi][ni][q] = 0.f; }

    issue_loads(0, 0);

    for (int s = 0; s < NSTAGE; s++) {
        const int buf = s & 1;
        if (s + 1 < NSTAGE) { issue_loads(s + 1, buf ^ 1); cp_wait1(); }
        else                { cp_wait0(); }
        __syncthreads();

        const uint32_t stage = smb + buf * STAGEB;
#pragma unroll
        for (int ks = 0; ks < 2; ks++) {
#pragma unroll
            for (int ai = 0; ai < 3; ai++) {
                const uint32_t Ab = stage + ai * TILEB;
                uint32_t a[4][4];
#pragma unroll
                for (int mi = 0; mi < 4; mi++)
                    ldm_x4(a[mi][0], a[mi][1], a[mi][2], a[mi][3],
                           Ab + (m_w + mi * 16) * ROWB + apos + ks * 32);
#pragma unroll
                for (int bi = 0; bi < 3; bi++) {
                    if (ai + bi > 2) continue;       // keep hh,hm,mh,hl,lh,mm
                    const uint32_t Bb = stage + (3 + bi) * TILEB;
                    uint32_t b[4][2];
#pragma unroll
                    for (int g = 0; g < 2; g++) {
                        uint32_t r0, r1, r2, r3;
                        ldm_x4(r0, r1, r2, r3,
                               Bb + (n_w + g * 16) * ROWB + bpos + ks * 32);
                        b[g * 2][0] = r0; b[g * 2][1] = r1;
                        b[g * 2 + 1][0] = r2; b[g * 2 + 1][1] = r3;
                    }
                    if (ai == 0 && bi == 0) {
#pragma unroll
                        for (int mi = 0; mi < 4; mi++)
#pragma unroll
                            for (int ni = 0; ni < 4; ni++)
                                mma16816(accH[mi][ni], a[mi], b[ni]);
                    } else {
#pragma unroll
                        for (int mi = 0; mi < 4; mi++)
#pragma unroll
                            for (int ni = 0; ni < 4; ni++)
                                mma16816(accL[mi][ni], a[mi], b[ni]);
                    }
                }
            }
        }
        __syncthreads();
    }

    // ---- epilogue: accH + accL, bias + relu -> g_h [m][p] ----
#pragma unroll
    for (int mi = 0; mi < 4; mi++) {
        const int row0 = m0 + m_w + mi * 16 + (l >> 2);
        const float bv0 = bias[row0];
        const float bv1 = bias[row0 + 8];
#pragma unroll
        for (int ni = 0; ni < 4; ni++) {
            const int col = n0 + n_w + ni * 8 + (l & 3) * 2;
            if (col < HW) {
                float c0 = accH[mi][ni][0] + accL[mi][ni][0];
                float c1 = accH[mi][ni][1] + accL[mi][ni][1];
                float c2 = accH[mi][ni][2] + accL[mi][ni][2];
                float c3 = accH[mi][ni][3] + accL[mi][ni][3];
                float2 v0 = make_float2(fmaxf(c0 + bv0, 0.f), fmaxf(c1 + bv0, 0.f));
                float2 v1 = make_float2(fmaxf(c2 + bv1, 0.f), fmaxf(c3 + bv1, 0.f));
                *reinterpret_cast<float2*>(&g_h[(size_t)row0 * HW + col]) = v0;
                *reinterpret_cast<float2*>(&g_h[(size_t)(row0 + 8) * HW + col]) = v1;
            }
        }
    }
}

// ---------------- fused 1x1 convs (score 18ch + loc 36ch) ----------------
__global__ __launch_bounds__(128) void k_1x1(const float* __restrict__ sw,
                                             const float* __restrict__ sb,
                                             const float* __restrict__ lw,
                                             const float* __restrict__ lb,
                                             float* __restrict__ out)
{
    __shared__ float ws[128][54];
    int p = blockIdx.x * 128 + threadIdx.x;
    bool ok = p < HW;
    float acc[54];
#pragma unroll
    for (int j = 0; j < 54; j++) acc[j] = 0.f;

    for (int cc = 0; cc < 512; cc += 128) {
        __syncthreads();
        for (int it = 0; it < 54; it++) {
            int cl = threadIdx.x;
            ws[cl][it] = (it < 18) ? sw[it * 512 + cc + cl]
                                   : lw[(it - 18) * 512 + cc + cl];
        }
        __syncthreads();
        if (ok) {
#pragma unroll 4
            for (int cl = 0; cl < 128; cl++) {
                float hv = g_h[(size_t)(cc + cl) * HW + p];
#pragma unroll
                for (int j = 0; j < 54; j++) acc[j] = fmaf(ws[cl][j], hv, acc[j]);
            }
        }
    }
    if (ok) {
#pragma unroll
        for (int j = 0; j < 18; j++) out[OUT_SC + p * 18 + j] = acc[j] + sb[j];
#pragma unroll
        for (int j = 0; j < 36; j++) out[OUT_LOC + p * 36 + j] = acc[18 + j] + lb[j];
    }
}

// ---------------- decode ----------------
__global__ void k_decode(const float* __restrict__ out)
{
    int i = blockIdx.x * 256 + threadIdx.x;
    if (i >= NBOX) return;
    int p = i / 9;
    int a = i - p * 9;
    int yy = p / WFE;
    int xx = p - yy * WFE;

    const double RS[3] = {0.5, 1.0, 2.0};
    const double SS[3] = {8.0, 16.0, 32.0};
    int ir = a / 3, js = a - ir * 3;
    double hh = 16.0 * SS[js] * sqrt(RS[ir]);
    double wa = 16.0 * SS[js] * sqrt(1.0 / RS[ir]);
    float sy = (float)(yy * 16);
    float sx = (float)(xx * 16);
    float A0 = sy + (float)(8.0 - hh * 0.5);
    float A1 = sx + (float)(8.0 - wa * 0.5);
    float A2 = sy + (float)(8.0 + hh * 0.5);
    float A3 = sx + (float)(8.0 + wa * 0.5);

    float h = A2 - A0, w = A3 - A1;
    float cy = A0 + 0.5f * h, cx = A1 + 0.5f * w;
    float dy = out[OUT_LOC + p * 36 + a * 4 + 0];
    float dx = out[OUT_LOC + p * 36 + a * 4 + 1];
    float dh = out[OUT_LOC + p * 36 + a * 4 + 2];
    float dw = out[OUT_LOC + p * 36 + a * 4 + 3];
    float cy2 = dy * h + cy;
    float cx2 = dx * w + cx;
    float h2 = expf(dh) * h;
    float w2 = expf(dw) * w;
    float r0 = fminf(fmaxf(cy2 - 0.5f * h2, 0.f), IMG_H);
    float r1 = fminf(fmaxf(cx2 - 0.5f * w2, 0.f), IMG_W);
    float r2 = fminf(fmaxf(cy2 + 0.5f * h2, 0.f), IMG_H);
    float r3 = fminf(fmaxf(cx2 + 0.5f * w2, 0.f), IMG_W);
    bool valid = (r2 - r0 >= 16.f) && (r3 - r1 >= 16.f);

    float s0 = out[OUT_SC + p * 18 + a * 2];
    float s1 = out[OUT_SC + p * 18 + a * 2 + 1];
    float mm = fmaxf(s0, s1);
    float e0 = expf(s0 - mm), e1 = expf(s1 - mm);
    float fg = e1 / (e0 + e1);

    g_roi[i * 4 + 0] = r0;
    g_roi[i * 4 + 1] = r1;
    g_roi[i * 4 + 2] = r2;
    g_roi[i * 4 + 3] = r3;
    g_sc[i] = valid ? fg : NEG_INF;
    g_idx[i] = (unsigned)i;
}

// ---------------- greedy NMS ----------------
__global__ void k_nms(float* __restrict__ out)
{
    extern __shared__ float smn[];
    float* ssc = smn;
    float* sy1 = smn + NPRE;
    float* sx1 = smn + 2 * NPRE;
    float* sy2 = smn + 3 * NPRE;
    float* sx2 = smn + 4 * NPRE;
    float* sar = smn + 5 * NPRE;
    __shared__ int ksel[NPOST];

    int tid = threadIdx.x;
    for (int i = tid; i < NPRE; i += 256) {
        unsigned idx = g_idx_s[i];
        float4 b = reinterpret_cast<const float4*>(g_roi)[idx];
        ssc[i] = g_sc_s[i];
        sy1[i] = b.x; sx1[i] = b.y; sy2[i] = b.z; sx2[i] = b.w;
        sar[i] = (b.z - b.x) * (b.w - b.y);
    }
    __syncthreads();

    int kc = 0;
    for (int i = 0; i < NPRE; i++) {
        float sc = ssc[i];
        if (sc == NEG_INF) break;
        float y1 = sy1[i], x1 = sx1[i], y2 = sy2[i], x2 = sx2[i], ar = sar[i];
        int sup = 0;
        for (int j = tid; j < kc; j += 256) {
            int t = ksel[j];
            float ih = fmaxf(fminf(sy2[t], y2) - fmaxf(sy1[t], y1), 0.f);
            float iw = fmaxf(fminf(sx2[t], x2) - fmaxf(sx1[t], x1), 0.f);
            float inter = ih * iw;
            float iou = inter / (sar[t] + ar - inter + 1e-9f);
            if (iou > 0.7f) sup = 1;
        }
        sup = __syncthreads_or(sup);
        if (!sup) {
            if (tid == 0) ksel[kc] = i;
            kc++;
            __syncthreads();
            if (kc == NPOST) break;
        }
    }

    for (int r = tid; r < NPOST; r += 256) {
        float v0 = 0.f, v1 = 0.f, v2 = 0.f, v3 = 0.f;
        if (r < kc) {
            int t = ksel[r];
            v0 = sy1[t]; v1 = sx1[t]; v2 = sy2[t]; v3 = sx2[t];
        }
        out[OUT_ROI + r * 4 + 0] = v0;
        out[OUT_ROI + r * 4 + 1] = v1;
        out[OUT_ROI + r * 4 + 2] = v2;
        out[OUT_ROI + r * 4 + 3] = v3;
    }
}

// ---------------- host launcher ----------------
extern "C" void kernel_launch(void* const* d_in, const int* in_sizes, int n_in,
                              void* d_out, int out_size)
{
    const float* x  = (const float*)d_in[0];
    const float* w1 = (const float*)d_in[1];
    const float* b1 = (const float*)d_in[2];
    const float* sw = (const float*)d_in[3];
    const float* sb = (const float*)d_in[4];
    const float* lw = (const float*)d_in[5];
    const float* lb = (const float*)d_in[6];
    float* out = (float*)d_out;

    int fill_n4 = PADHW * 512 / 8;
    k_fill<<<(fill_n4 + 255) / 256, 256>>>();
    k_xsplit<<<dim3(HW / 32, 512 / 32), dim3(32, 32)>>>(x);
    k_wsplit<<<512, 256>>>(w1);

    cudaFuncSetAttribute(k_convmma, cudaFuncAttributeMaxDynamicSharedMemorySize, SMEM_CONV);
    k_convmma<<<dim3((HW + TN - 1) / TN, CMID / TM), 256, SMEM_CONV>>>(b1);

    k_1x1<<<(HW + 127) / 128, 128>>>(sw, sb, lw, lb, out);
    k_decode<<<(NBOX + 255) / 256, 256>>>(out);

    void *p_sc, *p_idx, *p_scs, *p_idxs, *p_tmp;
    cudaGetSymbolAddress(&p_sc, g_sc);
    cudaGetSymbolAddress(&p_idx, g_idx);
    cudaGetSymbolAddress(&p_scs, g_sc_s);
    cudaGetSymbolAddress(&p_idxs, g_idx_s);
    cudaGetSymbolAddress(&p_tmp, g_tmp);

    size_t tb = 0;
    cub::DeviceRadixSort::SortPairsDescending(nullptr, tb,
        (const float*)p_sc, (float*)p_scs,
        (const unsigned*)p_idx, (unsigned*)p_idxs, NBOX);
    if (tb > (size_t)(32u << 20)) tb = (size_t)(32u << 20);
    cub::DeviceRadixSort::SortPairsDescending(p_tmp, tb,
        (const float*)p_sc, (float*)p_scs,
        (const unsigned*)p_idx, (unsigned*)p_idxs, NBOX);

    int nms_smem = 6 * NPRE * (int)sizeof(float);
    cudaFuncSetAttribute(k_nms, cudaFuncAttributeMaxDynamicSharedMemorySize, nms_smem);
    k_nms<<<1, 256, nms_smem>>>(out);
}

// round 10
// speedup vs baseline: 1.2933x; 1.2933x over previous
#include <cuda_runtime.h>
#include <cuda_fp16.h>
#include <cub/cub.cuh>
#include <math.h>

#define HFE 100
#define WFE 152
#define HW  15200
#define CMID 512
#define KTOT 4608           // 9 taps * 512 channels
#define PADH 102
#define PADW 154
#define PADHW (PADH*PADW)   // 15708
#define NBOX 136800
#define NPRE 6000
#define NPOST 300
#define OUT_LOC 0
#define OUT_SC  547200
#define OUT_ROI 820800
#define IMG_H 1600.0f
#define IMG_W 2432.0f
#define NEG_INF (__int_as_float(0xff800000))

// conv tiling
#define TM 128
#define TN 128
#define ROWB 80              // padded row bytes (32 fp16 = 64B data + 16B pad)
#define TILEB (128*ROWB)     // 10240 per tile
#define NTILE 4              // Ah Al Bh Bl
#define STAGEB (NTILE*TILEB) // 40960
#define NBUF 2
#define NSTAGE 144           // 9 taps * 16 channel-chunks (32ch each)
#define SMEM_SUM (NBUF*STAGEB)          // 81920
#define SMEM_ERR (SMEM_SUM + 65536)     // 147456
#define SMEM_CONV (SMEM_ERR + 65536)    // 212992

// recombination scales: accH holds 64*(wh*xh); accL holds 2^17*(wh*xl + wl*xh)
#define SCALE_H 0.015625f            // 2^-6
#define SCALE_L 7.62939453125e-6f    // 2^-17

// ---------------- device scratch ----------------
__device__ __align__(256) __half g_wh[CMID * KTOT];   // [m][k], k=t*512+c, = rn(64w)
__device__ __align__(256) __half g_wl[CMID * KTOT];   // rn((64w-wh)*2^11)
__device__ __align__(256) __half g_xh[PADHW * 512];   // [padrow][c], = rn(x)
__device__ __align__(256) __half g_xl[PADHW * 512];   // rn((x-xh)*2^11)
__device__ __align__(16)  float g_h[(size_t)CMID * HW];  // conv1 out [m][p]
__device__ float g_roi[NBOX * 4];
__device__ float g_sc[NBOX];
__device__ unsigned g_idx[NBOX];
__device__ float g_sc_s[NBOX];
__device__ unsigned g_idx_s[NBOX];
__device__ unsigned char g_tmp[32 << 20];

__constant__ int c_dy[9] = {-1,-1,-1, 0,0,0, 1,1,1};
__constant__ int c_dx[9] = {-1, 0, 1,-1,0,1,-1,0,1};

// ---------------- PTX helpers (compute_103-safe) ----------------
__device__ __forceinline__ uint32_t smem_u32(const void* p) {
    uint32_t a;
    asm("{ .reg .u64 t; cvta.to.shared.u64 t, %1; cvt.u32.u64 %0, t; }" : "=r"(a) : "l"(p));
    return a;
}
__device__ __forceinline__ void cp16(uint32_t dst, const void* src) {
    asm volatile("cp.async.cg.shared.global [%0], [%1], 16;" :: "r"(dst), "l"(src));
}
__device__ __forceinline__ void cp_commit() {
    asm volatile("cp.async.commit_group;" ::: "memory");
}
__device__ __forceinline__ void cp_wait1() {
    asm volatile("cp.async.wait_group 1;" ::: "memory");
}
__device__ __forceinline__ void cp_wait0() {
    asm volatile("cp.async.wait_group 0;" ::: "memory");
}
__device__ __forceinline__ void ldm_x4(uint32_t& r0, uint32_t& r1, uint32_t& r2, uint32_t& r3,
                                       uint32_t a) {
    asm volatile("ldmatrix.sync.aligned.m8n8.x4.shared.b16 {%0,%1,%2,%3}, [%4];"
                 : "=r"(r0), "=r"(r1), "=r"(r2), "=r"(r3) : "r"(a));
}
__device__ __forceinline__ void mma16816h(float* c, const uint32_t* a, const uint32_t* b) {
    asm volatile(
        "mma.sync.aligned.m16n8k16.row.col.f32.f16.f16.f32 "
        "{%0,%1,%2,%3}, {%4,%5,%6,%7}, {%8,%9}, {%0,%1,%2,%3};"
        : "+f"(c[0]), "+f"(c[1]), "+f"(c[2]), "+f"(c[3])
        : "r"(a[0]), "r"(a[1]), "r"(a[2]), "r"(a[3]), "r"(b[0]), "r"(b[1]));
}

// ---------------- prep: zero padded x arrays ----------------
__global__ void k_fill()
{
    int i = blockIdx.x * 256 + threadIdx.x;
    uint4 z = make_uint4(0, 0, 0, 0);
    int n4 = PADHW * 512 / 8;
    if (i < n4) {
        reinterpret_cast<uint4*>(g_xh)[i] = z;
        reinterpret_cast<uint4*>(g_xl)[i] = z;
    }
}

// ---------------- prep: x fp16 2-term split + transpose + pad ----------------
__global__ void k_xsplit(const float* __restrict__ x)
{
    __shared__ float tile[32][33];
    int p0 = blockIdx.x * 32;
    int c0 = blockIdx.y * 32;
    int tx = threadIdx.x, ty = threadIdx.y;
    tile[ty][tx] = x[(c0 + ty) * HW + p0 + tx];
    __syncthreads();
    int p = p0 + ty;
    int py = p / WFE, px = p - py * WFE;
    int row = (py + 1) * PADW + px + 1;
    float v = tile[tx][ty];
    __half hi = __float2half_rn(v);
    __half lo = __float2half_rn((v - __half2float(hi)) * 2048.0f);
    g_xh[row * 512 + c0 + tx] = hi;
    g_xl[row * 512 + c0 + tx] = lo;
}

// ---------------- prep: weight fp16 2-term split (x64 scaled) + reorder -------
__global__ void k_wsplit(const float* __restrict__ w1)
{
    __shared__ float wrow[KTOT];
    int m = blockIdx.x;
    for (int i = threadIdx.x; i < KTOT; i += 256)
        wrow[i] = w1[m * KTOT + i];           // [c][t] order
    __syncthreads();
    for (int j = threadIdx.x; j < KTOT; j += 256) {
        int t = j >> 9, c = j & 511;
        float v = wrow[c * 9 + t] * 64.0f;
        __half hi = __float2half_rn(v);
        __half lo = __float2half_rn((v - __half2float(hi)) * 2048.0f);
        g_wh[m * KTOT + j] = hi;
        g_wl[m * KTOT + j] = lo;
    }
}

// ---------------- conv 3x3 via mma.sync fp16 (2-term split, 3 products) -------
// hh -> accH, drained every 2 stages into a smem TwoSum pair (sum, err) to
// suppress long-chain fp32 accumulation noise. hl+lh -> accL (scale 2^-17,
// register-resident; its chain noise is 2^-11 down). ll neglected (~2^-22).
__global__ __launch_bounds__(256, 1) void k_convmma(const float* __restrict__ bias)
{
    extern __shared__ char smc[];
    const uint32_t smb = smem_u32(smc);
    const int tid = threadIdx.x;
    const int n0 = blockIdx.x * TN;
    const int m0 = blockIdx.y * TM;

    float4* sumS = reinterpret_cast<float4*>(smc + SMEM_SUM);   // [16][256]
    float4* errS = reinterpret_cast<float4*>(smc + SMEM_ERR);   // [16][256]
    {
        float4 z = make_float4(0.f, 0.f, 0.f, 0.f);
#pragma unroll
        for (int g = 0; g < 16; g++) { sumS[g * 256 + tid] = z; errS[g * 256 + tid] = z; }
    }

    // ---- loader geometry: 2 row-tasks per thread (4 tiles x 128 rows / 256) ----
    int task_tile[2];
    const __half* task_base[2];
    uint32_t task_dst[2];
#pragma unroll
    for (int j = 0; j < 2; j++) {
        int r = j * 256 + tid;
        int tile = r >> 7;        // 0:Ah 1:Al 2:Bh 3:Bl
        int row = r & 127;
        task_tile[j] = tile;
        task_dst[j] = smb + tile * TILEB + row * ROWB;
        if (tile < 2) {
            const __half* gw = (tile == 0) ? g_wh : g_wl;
            task_base[j] = gw + (size_t)(m0 + row) * KTOT;
        } else {
            const __half* gx = (tile == 2) ? g_xh : g_xl;
            int p = min(n0 + row, HW - 1);
            int py = p / WFE, px = p - py * WFE;
            task_base[j] = gx + (size_t)((py + 1) * PADW + px + 1) * 512;
        }
    }

    auto issue_loads = [&](int s) {
        const int t = s >> 4;
        const int c0 = (s & 15) << 5;
        const int woff = t * 512 + c0;
        const int xoff = (c_dy[t] * PADW + c_dx[t]) * 512 + c0;
        const uint32_t boff = (s & 1) * STAGEB;
#pragma unroll
        for (int j = 0; j < 2; j++) {
            const __half* p = task_base[j] + (task_tile[j] < 2 ? woff : xoff);
            uint32_t d = task_dst[j] + boff;
#pragma unroll
            for (int q = 0; q < 4; q++) cp16(d + q * 16, p + q * 8);
        }
        cp_commit();
    };

    // ---- compute geometry ----
    const int w = tid >> 5;
    const int l = tid & 31;
    const int m_w = (w >> 2) * 64;    // 0 or 64
    const int n_w = (w & 3) * 32;     // 0,32,64,96
    const uint32_t apos = ((l & 7) + ((l >> 3) & 1) * 8) * ROWB + (l >> 4) * 16;
    const uint32_t bpos = ((l & 7) + (l >> 4) * 8) * ROWB + ((l >> 3) & 1) * 16;

    float accH[4][4][4];
    float accL[4][4][4];
#pragma unroll
    for (int mi = 0; mi < 4; mi++)
#pragma unroll
        for (int ni = 0; ni < 4; ni++)
#pragma unroll
            for (int q = 0; q < 4; q++) { accH[mi][ni][q] = 0.f; accL[mi][ni][q] = 0.f; }

    issue_loads(0);
    issue_loads(1);

    for (int s = 0; s < NSTAGE; s++) {
        if (s < NSTAGE - 1) cp_wait1(); else cp_wait0();
        __syncthreads();

        const uint32_t stage = smb + (s & 1) * STAGEB;
        const uint32_t Ah = stage;
        const uint32_t Al = stage + TILEB;
        const uint32_t Bh = stage + 2 * TILEB;
        const uint32_t Bl = stage + 3 * TILEB;
#pragma unroll
        for (int ks = 0; ks < 2; ks++) {
            uint32_t ah[4][4], al[4][4];
#pragma unroll
            for (int mi = 0; mi < 4; mi++) {
                ldm_x4(ah[mi][0], ah[mi][1], ah[mi][2], ah[mi][3],
                       Ah + (m_w + mi * 16) * ROWB + apos + ks * 32);
                ldm_x4(al[mi][0], al[mi][1], al[mi][2], al[mi][3],
                       Al + (m_w + mi * 16) * ROWB + apos + ks * 32);
            }
            uint32_t bh[4][2], bl[4][2];
#pragma unroll
            for (int g = 0; g < 2; g++) {
                uint32_t r0, r1, r2, r3;
                ldm_x4(r0, r1, r2, r3, Bh + (n_w + g * 16) * ROWB + bpos + ks * 32);
                bh[g * 2][0] = r0; bh[g * 2][1] = r1;
                bh[g * 2 + 1][0] = r2; bh[g * 2 + 1][1] = r3;
                ldm_x4(r0, r1, r2, r3, Bl + (n_w + g * 16) * ROWB + bpos + ks * 32);
                bl[g * 2][0] = r0; bl[g * 2][1] = r1;
                bl[g * 2 + 1][0] = r2; bl[g * 2 + 1][1] = r3;
            }
#pragma unroll
            for (int mi = 0; mi < 4; mi++)
#pragma unroll
                for (int ni = 0; ni < 4; ni++) {
                    mma16816h(accH[mi][ni], ah[mi], bh[ni]);
                    mma16816h(accL[mi][ni], ah[mi], bl[ni]);
                    mma16816h(accL[mi][ni], al[mi], bh[ni]);
                }
        }

        // ---- compensated drain of accH every 2 stages (TwoSum into smem) ----
        if (s & 1) {
#pragma unroll
            for (int g = 0; g < 16; g++) {
                const int mi = g >> 2, ni = g & 3;
                float4 s4 = sumS[g * 256 + tid];
                float4 e4 = errS[g * 256 + tid];
                float* sp = reinterpret_cast<float*>(&s4);
                float* ep = reinterpret_cast<float*>(&e4);
#pragma unroll
                for (int q = 0; q < 4; q++) {
                    float a = accH[mi][ni][q];
                    float t = sp[q] + a;
                    float bp = t - sp[q];
                    ep[q] += (sp[q] - (t - bp)) + (a - bp);
                    sp[q] = t;
                    accH[mi][ni][q] = 0.f;
                }
                sumS[g * 256 + tid] = s4;
                errS[g * 256 + tid] = e4;
            }
        }

        __syncthreads();
        if (s + 2 < NSTAGE) issue_loads(s + 2);
    }

    // ---- epilogue: (sum+err)*2^-6 + accL*2^-17, bias + relu -> g_h [m][p] ----
#pragma unroll
    for (int mi = 0; mi < 4; mi++) {
        const int row0 = m0 + m_w + mi * 16 + (l >> 2);
        const float bv0 = bias[row0];
        const float bv1 = bias[row0 + 8];
#pragma unroll
        for (int ni = 0; ni < 4; ni++) {
            const int g = mi * 4 + ni;
            float4 s4 = sumS[g * 256 + tid];
            float4 e4 = errS[g * 256 + tid];
            const int col = n0 + n_w + ni * 8 + (l & 3) * 2;
            if (col < HW) {
                float h0 = s4.x + e4.x;
                float h1 = s4.y + e4.y;
                float h2 = s4.z + e4.z;
                float h3 = s4.w + e4.w;
                float c0 = fmaf(accL[mi][ni][0], SCALE_L, h0 * SCALE_H);
                float c1 = fmaf(accL[mi][ni][1], SCALE_L, h1 * SCALE_H);
                float c2 = fmaf(accL[mi][ni][2], SCALE_L, h2 * SCALE_H);
                float c3 = fmaf(accL[mi][ni][3], SCALE_L, h3 * SCALE_H);
                float2 v0 = make_float2(fmaxf(c0 + bv0, 0.f), fmaxf(c1 + bv0, 0.f));
                float2 v1 = make_float2(fmaxf(c2 + bv1, 0.f), fmaxf(c3 + bv1, 0.f));
                *reinterpret_cast<float2*>(&g_h[(size_t)row0 * HW + col]) = v0;
                *reinterpret_cast<float2*>(&g_h[(size_t)(row0 + 8) * HW + col]) = v1;
            }
        }
    }
}

// ---------------- fused 1x1 convs (score 18ch + loc 36ch) ----------------
__global__ __launch_bounds__(128) void k_1x1(const float* __restrict__ sw,
                                             const float* __restrict__ sb,
                                             const float* __restrict__ lw,
                                             const float* __restrict__ lb,
                                             float* __restrict__ out)
{
    __shared__ float ws[128][54];
    int p = blockIdx.x * 128 + threadIdx.x;
    bool ok = p < HW;
    float acc[54];
#pragma unroll
    for (int j = 0; j < 54; j++) acc[j] = 0.f;

    for (int cc = 0; cc < 512; cc += 128) {
        __syncthreads();
        for (int it = 0; it < 54; it++) {
            int cl = threadIdx.x;
            ws[cl][it] = (it < 18) ? sw[it * 512 + cc + cl]
                                   : lw[(it - 18) * 512 + cc + cl];
        }
        __syncthreads();
        if (ok) {
#pragma unroll 4
            for (int cl = 0; cl < 128; cl++) {
                float hv = g_h[(size_t)(cc + cl) * HW + p];
#pragma unroll
                for (int j = 0; j < 54; j++) acc[j] = fmaf(ws[cl][j], hv, acc[j]);
            }
        }
    }
    if (ok) {
#pragma unroll
        for (int j = 0; j < 18; j++) out[OUT_SC + p * 18 + j] = acc[j] + sb[j];
#pragma unroll
        for (int j = 0; j < 36; j++) out[OUT_LOC + p * 36 + j] = acc[18 + j] + lb[j];
    }
}

// ---------------- decode ----------------
__global__ void k_decode(const float* __restrict__ out)
{
    int i = blockIdx.x * 256 + threadIdx.x;
    if (i >= NBOX) return;
    int p = i / 9;
    int a = i - p * 9;
    int yy = p / WFE;
    int xx = p - yy * WFE;

    const double RS[3] = {0.5, 1.0, 2.0};
    const double SS[3] = {8.0, 16.0, 32.0};
    int ir = a / 3, js = a - ir * 3;
    double hh = 16.0 * SS[js] * sqrt(RS[ir]);
    double wa = 16.0 * SS[js] * sqrt(1.0 / RS[ir]);
    float sy = (float)(yy * 16);
    float sx = (float)(xx * 16);
    float A0 = sy + (float)(8.0 - hh * 0.5);
    float A1 = sx + (float)(8.0 - wa * 0.5);
    float A2 = sy + (float)(8.0 + hh * 0.5);
    float A3 = sx + (float)(8.0 + wa * 0.5);

    float h = A2 - A0, w = A3 - A1;
    float cy = A0 + 0.5f * h, cx = A1 + 0.5f * w;
    float dy = out[OUT_LOC + p * 36 + a * 4 + 0];
    float dx = out[OUT_LOC + p * 36 + a * 4 + 1];
    float dh = out[OUT_LOC + p * 36 + a * 4 + 2];
    float dw = out[OUT_LOC + p * 36 + a * 4 + 3];
    float cy2 = dy * h + cy;
    float cx2 = dx * w + cx;
    float h2 = expf(dh) * h;
    float w2 = expf(dw) * w;
    float r0 = fminf(fmaxf(cy2 - 0.5f * h2, 0.f), IMG_H);
    float r1 = fminf(fmaxf(cx2 - 0.5f * w2, 0.f), IMG_W);
    float r2 = fminf(fmaxf(cy2 + 0.5f * h2, 0.f), IMG_H);
    float r3 = fminf(fmaxf(cx2 + 0.5f * w2, 0.f), IMG_W);
    bool valid = (r2 - r0 >= 16.f) && (r3 - r1 >= 16.f);

    float s0 = out[OUT_SC + p * 18 + a * 2];
    float s1 = out[OUT_SC + p * 18 + a * 2 + 1];
    float mm = fmaxf(s0, s1);
    float e0 = expf(s0 - mm), e1 = expf(s1 - mm);
    float fg = e1 / (e0 + e1);

    g_roi[i * 4 + 0] = r0;
    g_roi[i * 4 + 1] = r1;
    g_roi[i * 4 + 2] = r2;
    g_roi[i * 4 + 3] = r3;
    g_sc[i] = valid ? fg : NEG_INF;
    g_idx[i] = (unsigned)i;
}

// ---------------- greedy NMS ----------------
__global__ void k_nms(float* __restrict__ out)
{
    extern __shared__ float smn[];
    float* ssc = smn;
    float* sy1 = smn + NPRE;
    float* sx1 = smn + 2 * NPRE;
    float* sy2 = smn + 3 * NPRE;
    float* sx2 = smn + 4 * NPRE;
    float* sar = smn + 5 * NPRE;
    __shared__ int ksel[NPOST];

    int tid = threadIdx.x;
    for (int i = tid; i < NPRE; i += 256) {
        unsigned idx = g_idx_s[i];
        float4 b = reinterpret_cast<const float4*>(g_roi)[idx];
        ssc[i] = g_sc_s[i];
        sy1[i] = b.x; sx1[i] = b.y; sy2[i] = b.z; sx2[i] = b.w;
        sar[i] = (b.z - b.x) * (b.w - b.y);
    }
    __syncthreads();

    int kc = 0;
    for (int i = 0; i < NPRE; i++) {
        float sc = ssc[i];
        if (sc == NEG_INF) break;
        float y1 = sy1[i], x1 = sx1[i], y2 = sy2[i], x2 = sx2[i], ar = sar[i];
        int sup = 0;
        for (int j = tid; j < kc; j += 256) {
            int t = ksel[j];
            float ih = fmaxf(fminf(sy2[t], y2) - fmaxf(sy1[t], y1), 0.f);
            float iw = fmaxf(fminf(sx2[t], x2) - fmaxf(sx1[t], x1), 0.f);
            float inter = ih * iw;
            float iou = inter / (sar[t] + ar - inter + 1e-9f);
            if (iou > 0.7f) sup = 1;
        }
        sup = __syncthreads_or(sup);
        if (!sup) {
            if (tid == 0) ksel[kc] = i;
            kc++;
            __syncthreads();
            if (kc == NPOST) break;
        }
    }

    for (int r = tid; r < NPOST; r += 256) {
        float v0 = 0.f, v1 = 0.f, v2 = 0.f, v3 = 0.f;
        if (r < kc) {
            int t = ksel[r];
            v0 = sy1[t]; v1 = sx1[t]; v2 = sy2[t]; v3 = sx2[t];
        }
        out[OUT_ROI + r * 4 + 0] = v0;
        out[OUT_ROI + r * 4 + 1] = v1;
        out[OUT_ROI + r * 4 + 2] = v2;
        out[OUT_ROI + r * 4 + 3] = v3;
    }
}

// ---------------- host launcher ----------------
extern "C" void kernel_launch(void* const* d_in, const int* in_sizes, int n_in,
                              void* d_out, int out_size)
{
    const float* x  = (const float*)d_in[0];
    const float* w1 = (const float*)d_in[1];
    const float* b1 = (const float*)d_in[2];
    const float* sw = (const float*)d_in[3];
    const float* sb = (const float*)d_in[4];
    const float* lw = (const float*)d_in[5];
    const float* lb = (const float*)d_in[6];
    float* out = (float*)d_out;

    int fill_n4 = PADHW * 512 / 8;
    k_fill<<<(fill_n4 + 255) / 256, 256>>>();
    k_xsplit<<<dim3(HW / 32, 512 / 32), dim3(32, 32)>>>(x);
    k_wsplit<<<512, 256>>>(w1);

    cudaFuncSetAttribute(k_convmma, cudaFuncAttributeMaxDynamicSharedMemorySize, SMEM_CONV);
    k_convmma<<<dim3((HW + TN - 1) / TN, CMID / TM), 256, SMEM_CONV>>>(b1);

    k_1x1<<<(HW + 127) / 128, 128>>>(sw, sb, lw, lb, out);
    k_decode<<<(NBOX + 255) / 256, 256>>>(out);

    void *p_sc, *p_idx, *p_scs, *p_idxs, *p_tmp;
    cudaGetSymbolAddress(&p_sc, g_sc);
    cudaGetSymbolAddress(&p_idx, g_idx);
    cudaGetSymbolAddress(&p_scs, g_sc_s);
    cudaGetSymbolAddress(&p_idxs, g_idx_s);
    cudaGetSymbolAddress(&p_tmp, g_tmp);

    size_t tb = 0;
    cub::DeviceRadixSort::SortPairsDescending(nullptr, tb,
        (const float*)p_sc, (float*)p_scs,
        (const unsigned*)p_idx, (unsigned*)p_idxs, NBOX);
    if (tb > (size_t)(32u << 20)) tb = (size_t)(32u << 20);
    cub::DeviceRadixSort::SortPairsDescending(p_tmp, tb,
        (const float*)p_sc, (float*)p_scs,
        (const unsigned*)p_idx, (unsigned*)p_idxs, NBOX);

    int nms_smem = 6 * NPRE * (int)sizeof(float);
    cudaFuncSetAttribute(k_nms, cudaFuncAttributeMaxDynamicSharedMemorySize, nms_smem);
    k_nms<<<1, 256, nms_smem>>>(out);
}